// round 4
// baseline (speedup 1.0000x reference)
#include <cuda_runtime.h>
#include <cstddef>

#define NE 1600000
#define NV 100000
#define NCHUNK 400000          // NE/4
#define NLAYER 20
#define BN_EPS 1e-5f
#define NT 256
#define NSM 148
#define BPSM 3
#define NBLK (NSM * BPSM)      // 444 blocks, guaranteed co-resident
#define NTH (NBLK * NT)        // 113664 threads
#define MAXIT 4                // ceil(NCHUNK / NTH)
#define SMEM_SZ (MAXIT * 4 * NT * 16)   // 65536 B: float4 per edge per iter

// ---------------- constant weights ----------------
struct CW {
    float we_w1[36], we_b1[4], we_g1[4], we_be1[4], we_w2[12], we_b2[3];
    float wv_w1[18], wv_b1[3], wv_g1[3], wv_be1[3], wv_w2[9], wv_b2[3];
    float ow1[9], ob1[3], og[3], obe[3], ow2[6], ob2[2];
};
__constant__ CW cw;

// ---------------- persistent device state ----------------
__device__ float4 g_M[2][NV];
__device__ float  g_H[NE * 3];        // edge features (same-thread RW)
__device__ float  g_Z[NE * 3];        // zm scratch A->B (same-thread RW)
__device__ float  g_stats[24 * 16];   // per-layer BN stats; slot 20 = head
__device__ unsigned        g_count = 0;
__device__ volatile unsigned g_gen = 0;

// ---------------- software grid barrier ----------------
__device__ __forceinline__ void grid_sync() {
    __syncthreads();
    if (threadIdx.x == 0) {
        __threadfence();
        unsigned gen = g_gen;
        if (atomicInc(&g_count, NBLK - 1) == NBLK - 1) {
            __threadfence();
            g_gen = gen + 1;           // release
        } else {
            while (g_gen == gen) __nanosleep(64);
        }
        __threadfence();
    }
    __syncthreads();
}

__device__ __forceinline__ float wsum(float v) {
#pragma unroll
    for (int o = 16; o; o >>= 1) v += __shfl_xor_sync(0xffffffffu, v, o);
    return v;
}

// block-level reduce then one global atomic per channel per block
template <int K>
__device__ __forceinline__ void blk_stats(float* dst, float* v, float* bs) {
#pragma unroll
    for (int j = 0; j < K; j++) v[j] = wsum(v[j]);
    if (threadIdx.x < K) bs[threadIdx.x] = 0.f;
    __syncthreads();
    if ((threadIdx.x & 31) == 0) {
#pragma unroll
        for (int j = 0; j < K; j++) atomicAdd(&bs[j], v[j]);
    }
    __syncthreads();
    if (threadIdx.x < K) atomicAdd(&dst[threadIdx.x], bs[threadIdx.x]);
    __syncthreads();
}

// ---------------- the whole network in one kernel ----------------
__global__ void __launch_bounds__(NT, BPSM)
mega(const int* __restrict__ src, const int* __restrict__ dst,
     const float* __restrict__ Hin, const float* __restrict__ Min,
     float* __restrict__ out) {
    extern __shared__ float4 smE[];      // [ (it*4+k)*NT + tid ] : y (A->B) then z (B->C)
    __shared__ float bs[8];
    const int tid = threadIdx.x;
    const int gtid = blockIdx.x * NT + tid;

    // ---- init: pack M into float4 ----
    for (int i = gtid; i < NV; i += NTH)
        g_M[0][i] = make_float4(Min[3 * i], Min[3 * i + 1], Min[3 * i + 2], 0.f);
    grid_sync();

    for (int l = 0; l < NLAYER; l++) {
        const float4* __restrict__ Mc = g_M[l & 1];
        float4* __restrict__ Mn = g_M[(l & 1) ^ 1];
        const float* __restrict__ Hread = (l == 0) ? Hin : g_H;
        float* se = g_stats + l * 16;
        float* sv = se + 8;
        const int last = (l == NLAYER - 1);

        // ================= phase A: gather + e-MLP-1 + zm, e-stats =================
        if (!last) {
            for (int i = gtid; i < NV; i += NTH) Mn[i] = make_float4(0.f, 0.f, 0.f, 0.f);
        }
        {
            float acc[8] = {0.f,0.f,0.f,0.f,0.f,0.f,0.f,0.f};
            int it = 0;
            for (int c = gtid; c < NCHUNK; c += NTH, it++) {
                const int base = 4 * c;
                int4 s4 = __ldg((const int4*)(src + base));
                int4 d4 = __ldg((const int4*)(dst + base));
                float4 mi[4], mj[4];
                mi[0] = __ldcg(Mc + d4.x); mi[1] = __ldcg(Mc + d4.y);
                mi[2] = __ldcg(Mc + d4.z); mi[3] = __ldcg(Mc + d4.w);
                mj[0] = __ldcg(Mc + s4.x); mj[1] = __ldcg(Mc + s4.y);
                mj[2] = __ldcg(Mc + s4.z); mj[3] = __ldcg(Mc + s4.w);
                float4 ha = __ldg((const float4*)(Hread + 3 * base));
                float4 hb = __ldg((const float4*)(Hread + 3 * base + 4));
                float4 hc = __ldg((const float4*)(Hread + 3 * base + 8));
                float hh[12] = {ha.x,ha.y,ha.z,ha.w, hb.x,hb.y,hb.z,hb.w, hc.x,hc.y,hc.z,hc.w};
                float zz[12];
#pragma unroll
                for (int k = 0; k < 4; k++) {
                    float h0 = hh[3*k], h1 = hh[3*k+1], h2 = hh[3*k+2];
                    float y[4];
#pragma unroll
                    for (int j = 0; j < 4; j++) {
                        y[j] = cw.we_b1[j]
                             + mi[k].x*cw.we_w1[0*4+j] + mi[k].y*cw.we_w1[1*4+j] + mi[k].z*cw.we_w1[2*4+j]
                             + mj[k].x*cw.we_w1[3*4+j] + mj[k].y*cw.we_w1[4*4+j] + mj[k].z*cw.we_w1[5*4+j]
                             + h0*cw.we_w1[6*4+j] + h1*cw.we_w1[7*4+j] + h2*cw.we_w1[8*4+j];
                        acc[j] += y[j];
                        acc[4+j] += y[j] * y[j];
                    }
                    smE[(it*4+k)*NT + tid] = make_float4(y[0], y[1], y[2], y[3]);
#pragma unroll
                    for (int cc = 0; cc < 3; cc++) {
                        zz[3*k+cc] = cw.wv_b1[cc]
                            + mi[k].x*cw.wv_w1[0*3+cc] + mi[k].y*cw.wv_w1[1*3+cc] + mi[k].z*cw.wv_w1[2*3+cc];
                    }
                }
                float4* Zp = (float4*)(g_Z + 3 * base);
                Zp[0] = make_float4(zz[0],zz[1],zz[2],zz[3]);
                Zp[1] = make_float4(zz[4],zz[5],zz[6],zz[7]);
                Zp[2] = make_float4(zz[8],zz[9],zz[10],zz[11]);
            }
            blk_stats<8>(se, acc, bs);
        }
        grid_sync();

        // ================= phase B: e-BN -> Hn -> z, v-stats =================
        {
            float sc[4], sh[4];
#pragma unroll
            for (int j = 0; j < 4; j++) {
                float m = __ldcg(se + j) * (1.f / NE);
                float v = __ldcg(se + 4 + j) * (1.f / NE) - m * m;
                float r = rsqrtf(v + BN_EPS);
                sc[j] = r * cw.we_g1[j];
                sh[j] = cw.we_be1[j] - m * sc[j];
            }
            float acc[6] = {0.f,0.f,0.f,0.f,0.f,0.f};
            float hacc[6] = {0.f,0.f,0.f,0.f,0.f,0.f};
            int it = 0;
            for (int c = gtid; c < NCHUNK; c += NTH, it++) {
                const int base = 4 * c;
                const float4* Zp = (const float4*)(g_Z + 3 * base);
                float4 za = Zp[0], zb = Zp[1], zc = Zp[2];
                float zm[12] = {za.x,za.y,za.z,za.w, zb.x,zb.y,zb.z,zb.w, zc.x,zc.y,zc.z,zc.w};
                float hhn[12];
#pragma unroll
                for (int k = 0; k < 4; k++) {
                    float4 y4 = smE[(it*4+k)*NT + tid];
                    float tj[4];
                    tj[0] = fmaxf(fmaf(y4.x, sc[0], sh[0]), 0.f);
                    tj[1] = fmaxf(fmaf(y4.y, sc[1], sh[1]), 0.f);
                    tj[2] = fmaxf(fmaf(y4.z, sc[2], sh[2]), 0.f);
                    tj[3] = fmaxf(fmaf(y4.w, sc[3], sh[3]), 0.f);
                    float hn[3];
#pragma unroll
                    for (int cc = 0; cc < 3; cc++) {
                        hn[cc] = cw.we_b2[cc]
                               + tj[0]*cw.we_w2[0*3+cc] + tj[1]*cw.we_w2[1*3+cc]
                               + tj[2]*cw.we_w2[2*3+cc] + tj[3]*cw.we_w2[3*3+cc];
                        hhn[3*k+cc] = hn[cc];
                    }
                    float z0 = zm[3*k+0] + hn[0]*cw.wv_w1[3*3+0] + hn[1]*cw.wv_w1[4*3+0] + hn[2]*cw.wv_w1[5*3+0];
                    float z1 = zm[3*k+1] + hn[0]*cw.wv_w1[3*3+1] + hn[1]*cw.wv_w1[4*3+1] + hn[2]*cw.wv_w1[5*3+1];
                    float z2 = zm[3*k+2] + hn[0]*cw.wv_w1[3*3+2] + hn[1]*cw.wv_w1[4*3+2] + hn[2]*cw.wv_w1[5*3+2];
                    acc[0] += z0; acc[1] += z1; acc[2] += z2;
                    acc[3] += z0*z0; acc[4] += z1*z1; acc[5] += z2*z2;
                    smE[(it*4+k)*NT + tid] = make_float4(z0, z1, z2, 0.f);  // z replaces y
                    if (last) {
#pragma unroll
                        for (int cc = 0; cc < 3; cc++) {
                            float yh = cw.ob1[cc]
                                     + hn[0]*cw.ow1[0*3+cc] + hn[1]*cw.ow1[1*3+cc] + hn[2]*cw.ow1[2*3+cc];
                            hacc[cc] += yh;
                            hacc[3+cc] += yh * yh;
                        }
                    }
                }
                float4* Hp = (float4*)(g_H + 3 * base);
                Hp[0] = make_float4(hhn[0],hhn[1],hhn[2],hhn[3]);
                Hp[1] = make_float4(hhn[4],hhn[5],hhn[6],hhn[7]);
                Hp[2] = make_float4(hhn[8],hhn[9],hhn[10],hhn[11]);
            }
            blk_stats<6>(sv, acc, bs);
            if (last) blk_stats<6>(g_stats + 20 * 16, hacc, bs);
        }
        grid_sync();

        if (last) break;   // M_20 is never consumed: skip phase C entirely

        // ================= phase C: v-BN -> message -> scatter =================
        {
            float sc[3], sh[3];
#pragma unroll
            for (int cc = 0; cc < 3; cc++) {
                float m = __ldcg(sv + cc) * (1.f / NE);
                float v = __ldcg(sv + 3 + cc) * (1.f / NE) - m * m;
                float r = rsqrtf(v + BN_EPS);
                sc[cc] = r * cw.wv_g1[cc];
                sh[cc] = cw.wv_be1[cc] - m * sc[cc];
            }
            int it = 0;
            for (int c = gtid; c < NCHUNK; c += NTH, it++) {
                const int base = 4 * c;
                int4 d4 = __ldg((const int4*)(dst + base));
                int ids[4] = {d4.x, d4.y, d4.z, d4.w};
#pragma unroll
                for (int k = 0; k < 4; k++) {
                    float4 z4 = smE[(it*4+k)*NT + tid];
                    float t0 = fmaxf(fmaf(z4.x, sc[0], sh[0]), 0.f);
                    float t1 = fmaxf(fmaf(z4.y, sc[1], sh[1]), 0.f);
                    float t2 = fmaxf(fmaf(z4.z, sc[2], sh[2]), 0.f);
                    float m0 = cw.wv_b2[0] + t0*cw.wv_w2[0] + t1*cw.wv_w2[3] + t2*cw.wv_w2[6];
                    float m1 = cw.wv_b2[1] + t0*cw.wv_w2[1] + t1*cw.wv_w2[4] + t2*cw.wv_w2[7];
                    float m2 = cw.wv_b2[2] + t0*cw.wv_w2[2] + t1*cw.wv_w2[5] + t2*cw.wv_w2[8];
                    float* p = (float*)(Mn + ids[k]);
                    asm volatile("red.global.add.v4.f32 [%0], {%1,%2,%3,%4};"
                                 :: "l"(p), "f"(m0), "f"(m1), "f"(m2), "f"(0.f) : "memory");
                }
            }
        }
        grid_sync();
    }

    // ================= head: BN + ReLU + Linear(3,2) + softmax =================
    {
        const float* hs = g_stats + 20 * 16;
        float sc[3], sh[3];
#pragma unroll
        for (int cc = 0; cc < 3; cc++) {
            float m = __ldcg(hs + cc) * (1.f / NE);
            float v = __ldcg(hs + 3 + cc) * (1.f / NE) - m * m;
            float r = rsqrtf(v + BN_EPS);
            sc[cc] = r * cw.og[cc];
            sh[cc] = cw.obe[cc] - m * sc[cc];
        }
        for (int c = gtid; c < NCHUNK; c += NTH) {
            const int base = 4 * c;
            const float4* Hp = (const float4*)(g_H + 3 * base);
            float4 ha = Hp[0], hb = Hp[1], hc = Hp[2];
            float hh[12] = {ha.x,ha.y,ha.z,ha.w, hb.x,hb.y,hb.z,hb.w, hc.x,hc.y,hc.z,hc.w};
#pragma unroll
            for (int k = 0; k < 4; k++) {
                float tc[3];
#pragma unroll
                for (int cc = 0; cc < 3; cc++) {
                    float y = cw.ob1[cc]
                            + hh[3*k]*cw.ow1[0*3+cc] + hh[3*k+1]*cw.ow1[1*3+cc] + hh[3*k+2]*cw.ow1[2*3+cc];
                    tc[cc] = fmaxf(fmaf(y, sc[cc], sh[cc]), 0.f);
                }
                float l0 = cw.ob2[0] + tc[0]*cw.ow2[0] + tc[1]*cw.ow2[2] + tc[2]*cw.ow2[4];
                float l1 = cw.ob2[1] + tc[0]*cw.ow2[1] + tc[1]*cw.ow2[3] + tc[2]*cw.ow2[5];
                float mx = fmaxf(l0, l1);
                float e0 = __expf(l0 - mx);
                float e1 = __expf(l1 - mx);
                float inv = 1.f / (e0 + e1);
                ((float2*)out)[base + k] = make_float2(e0 * inv, e1 * inv);
            }
        }
    }
}

extern "C" void kernel_launch(void* const* d_in, const int* in_sizes, int n_in,
                              void* d_out, int out_size) {
    const float* M  = (const float*)d_in[0];
    const float* H  = (const float*)d_in[1];
    const int*   ei = (const int*)d_in[2];
    const int*   src = ei;
    const int*   dst = ei + NE;

    cudaMemcpyToSymbolAsync(cw, d_in[3],  36*4, offsetof(CW, we_w1), cudaMemcpyDeviceToDevice);
    cudaMemcpyToSymbolAsync(cw, d_in[4],   4*4, offsetof(CW, we_b1), cudaMemcpyDeviceToDevice);
    cudaMemcpyToSymbolAsync(cw, d_in[5],   4*4, offsetof(CW, we_g1), cudaMemcpyDeviceToDevice);
    cudaMemcpyToSymbolAsync(cw, d_in[6],   4*4, offsetof(CW, we_be1), cudaMemcpyDeviceToDevice);
    cudaMemcpyToSymbolAsync(cw, d_in[7],  12*4, offsetof(CW, we_w2), cudaMemcpyDeviceToDevice);
    cudaMemcpyToSymbolAsync(cw, d_in[8],   3*4, offsetof(CW, we_b2), cudaMemcpyDeviceToDevice);
    cudaMemcpyToSymbolAsync(cw, d_in[9],  18*4, offsetof(CW, wv_w1), cudaMemcpyDeviceToDevice);
    cudaMemcpyToSymbolAsync(cw, d_in[10],  3*4, offsetof(CW, wv_b1), cudaMemcpyDeviceToDevice);
    cudaMemcpyToSymbolAsync(cw, d_in[11],  3*4, offsetof(CW, wv_g1), cudaMemcpyDeviceToDevice);
    cudaMemcpyToSymbolAsync(cw, d_in[12],  3*4, offsetof(CW, wv_be1), cudaMemcpyDeviceToDevice);
    cudaMemcpyToSymbolAsync(cw, d_in[13],  9*4, offsetof(CW, wv_w2), cudaMemcpyDeviceToDevice);
    cudaMemcpyToSymbolAsync(cw, d_in[14],  3*4, offsetof(CW, wv_b2), cudaMemcpyDeviceToDevice);
    cudaMemcpyToSymbolAsync(cw, d_in[15],  9*4, offsetof(CW, ow1), cudaMemcpyDeviceToDevice);
    cudaMemcpyToSymbolAsync(cw, d_in[16],  3*4, offsetof(CW, ob1), cudaMemcpyDeviceToDevice);
    cudaMemcpyToSymbolAsync(cw, d_in[17],  3*4, offsetof(CW, og), cudaMemcpyDeviceToDevice);
    cudaMemcpyToSymbolAsync(cw, d_in[18],  3*4, offsetof(CW, obe), cudaMemcpyDeviceToDevice);
    cudaMemcpyToSymbolAsync(cw, d_in[19],  6*4, offsetof(CW, ow2), cudaMemcpyDeviceToDevice);
    cudaMemcpyToSymbolAsync(cw, d_in[20],  2*4, offsetof(CW, ob2), cudaMemcpyDeviceToDevice);

    void* p;
    cudaGetSymbolAddress(&p, g_stats);
    cudaMemsetAsync(p, 0, sizeof(float) * 24 * 16);

    static int smemSet = 0;
    if (!smemSet) {
        cudaFuncSetAttribute(mega, cudaFuncAttributeMaxDynamicSharedMemorySize, SMEM_SZ);
        smemSet = 1;
    }
    mega<<<NBLK, NT, SMEM_SZ>>>(src, dst, H, M, (float*)d_out);
}